// round 14
// baseline (speedup 1.0000x reference)
#include <cuda_runtime.h>
#include <math.h>

#define Bb 256
#define Nn 30
#define Ll 49
#define Vv 2000
#define WDc 300
#define Dd 256
#define NBc 64
#define Rr 50

// Output layout (concatenated flattened outputs in reference return order)
#define O_IMG 0
#define O_TGT (Bb*NBc)                  // 16384
#define O_WV  (2*Bb*NBc)                // 32768
#define O_SV  (O_WV + Bb*Nn*WDc)        // 2336768
#define O_ST  (O_SV + Bb*Ll)            // 2349312
#define O_SV2 (O_ST + Bb*Nn)            // 2356992
#define O_KG  (O_SV2 + Bb*Ll)           // 2369536

// Grid: [0,64) precompute | [64,576) interleaved batch/kg (even=batch, odd=kg)
#define G_PRE   64
#define G_BATCH 256
#define G_KG    256
#define G_TOTAL (G_PRE + G_BATCH + G_KG)

#define HS_S 260      // 65 x 16B units, 65%8==1 -> LDS.128 conflict-free
#define LG_S 33

__device__ float g_M[NBc*WDc];
__device__ float g_bb[NBc];
__device__ unsigned g_cnt;    // monotonic; never reset (g_M replay-invariant)

// NOTE: float4-accessed members (hs, iff, w1, w2) must sit at 16B-aligned
// offsets — keep them FIRST; scalar-only members follow.
struct __align__(16) SmemC {
    float hs[Nn][HS_S];     // offset 0          (31200 B, %16==0)
    float iff[Ll][HS_S];    // offset 31200      (50960 B, %16==0)
    float w1[Dd];           // offset 82160      (%16==0)
    float w2[Dd];           // offset 83184      (%16==0)
    float logits[Ll][LG_S]; // scalar access only
    float hsW1[Nn], tl[Nn], st[Nn];
    float v2l[Ll], svl[Ll], sv[Ll];
    float svwv[WDc];
    float oiv[Dd];
    int tgt[Nn];
};

__device__ __forceinline__ float fast_tanh(float x) {
    float r;
    asm("tanh.approx.f32 %0, %1;" : "=f"(r) : "f"(x));
    return r;
}

__device__ __forceinline__ float warp_red(float a) {
#pragma unroll
    for (int o = 16; o; o >>= 1) a += __shfl_xor_sync(0xffffffffu, a, o);
    return a;
}

__device__ __forceinline__ void fma2(unsigned long long& d,
                                     unsigned long long a,
                                     unsigned long long b) {
    asm("fma.rn.f32x2 %0, %1, %2, %0;" : "+l"(d) : "l"(a), "l"(b));
}

__device__ __forceinline__ float f32x2_hsum(unsigned long long a,
                                            unsigned long long b) {
    unsigned long long s;
    asm("add.rn.f32x2 %0, %1, %2;" : "=l"(s) : "l"(a), "l"(b));
    float lo, hi;
    asm("mov.b64 {%0, %1}, %2;" : "=f"(lo), "=f"(hi) : "l"(s));
    return lo + hi;
}

__device__ __forceinline__ float dot4(float4 a, float4 b) {
    return a.x * b.x + a.y * b.y + a.z * b.z + a.w * b.w;
}

__device__ __forceinline__ void warp_softmax(const float* src, float* dst_s,
                                             float* dst_g, int cnt, int lane) {
    float v0 = lane < cnt ? src[lane] : -1e30f;
    float v1 = (lane + 32) < cnt ? src[lane + 32] : -1e30f;
    float m = fmaxf(v0, v1);
#pragma unroll
    for (int o = 16; o; o >>= 1) m = fmaxf(m, __shfl_xor_sync(0xffffffffu, m, o));
    float e0 = lane < cnt ? __expf(v0 - m) : 0.f;
    float e1 = (lane + 32) < cnt ? __expf(v1 - m) : 0.f;
    float s = e0 + e1;
#pragma unroll
    for (int o = 16; o; o >>= 1) s += __shfl_xor_sync(0xffffffffu, s, o);
    float inv = 1.f / s;
    if (lane < cnt) {
        float r = e0 * inv;
        if (dst_s) dst_s[lane] = r;
        dst_g[lane] = r;
    }
    if (lane + 32 < cnt) {
        float r = e1 * inv;
        if (dst_s) dst_s[lane + 32] = r;
        dst_g[lane + 32] = r;
    }
}

// ---------------------------------------------------------------------------
// ONE kernel. Blocks: precompute | interleaved batch/kg (overlap latency
// -bound kg with compute-bound batch on every SM).
// ---------------------------------------------------------------------------
__global__ __launch_bounds__(768, 2) void fused_kernel(
    const float* __restrict__ rel, const float* __restrict__ wv,
    const float* __restrict__ img_feat, const float* __restrict__ hs_g,
    const float* __restrict__ tat,
    const float* __restrict__ Wc, const float* __restrict__ bc,
    const float* __restrict__ W1, const float* __restrict__ W2,
    const float* __restrict__ Whi, const float* __restrict__ bhi,
    const float* __restrict__ Wht, const float* __restrict__ bht,
    const int* __restrict__ targets, const int* __restrict__ lengths,
    float* __restrict__ out) {
    extern __shared__ char smem_raw[];
    int bid = blockIdx.x;
    int tid = threadIdx.x;
    int lane = tid & 31, wid = tid >> 5;

    // ======================= PRECOMPUTE PART (wave-0 blocks) ===============
    if (bid < G_PRE) {
        float* s_wht = (float*)smem_raw;     // 256 floats
        int k = bid;
        if (tid < Dd) s_wht[tid] = Wht[k * Dd + tid];
        __syncthreads();
        if (tid < WDc) {
            float acc = 0.f;
#pragma unroll 16
            for (int c = 0; c < Dd; c++)
                acc += s_wht[c] * __ldg(&Wc[c * WDc + tid]);
            g_M[k * WDc + tid] = acc;
        }
        if (wid == 0) {
            float a = 0.f;
#pragma unroll
            for (int c = lane; c < Dd; c += 32) a += s_wht[c] * bc[c];
            a = warp_red(a);
            if (lane == 0) g_bb[k] = a + bht[k];
        }
        __syncthreads();
        if (tid == 0) {
            __threadfence();
            atomicAdd(&g_cnt, 1u);
        }
        return;
    }

    int q = bid - G_PRE;          // [0, 512)
    int b = q >> 1;               // batch index for both roles

    // ======================= KG PART (odd q) ===============================
    // 1 block per b; 2 chunks of 15 i's; 15 loads in flight before stores.
    if (q & 1) {
        int* s_tj = (int*)smem_raw;
        __shared__ int s_len;
        if (tid < Nn) s_tj[tid] = targets[b * Nn + tid] - 4;
        if (tid == 0) s_len = lengths[b];
        __syncthreads();
        if (tid >= 750) return;
        int j = tid / 25;
        int r2 = tid - j * 25;
        int len = s_len;
        int c0 = s_tj[j] * 25 + r2;
        int lim = (j < len) ? len : 0;
        const float2* rel2 = (const float2*)rel;
        float2* o = (float2*)(out + O_KG) + (size_t)b * (Nn * 750) + tid;
#pragma unroll
        for (int ch = 0; ch < 2; ch++) {
            int i0 = ch * 15;
            float2 v[15];
#pragma unroll
            for (int k = 0; k < 15; k++) {
                int i = i0 + k;
                v[k] = make_float2(0.f, 0.f);
                if (i < lim) v[k] = rel2[s_tj[i] * 50000 + c0];
            }
#pragma unroll
            for (int k = 0; k < 15; k++) o[(i0 + k) * 750] = v[k];
        }
        return;
    }

    // ======================= BATCH PART (even q) ===========================
    SmemC& s = *(SmemC*)smem_raw;

    // ---- load phase ----
    const float4* hs4 = (const float4*)(hs_g + (size_t)b * Nn * Dd);
    for (int i = tid; i < Nn * 64; i += 768) {
        int n = i >> 6, c4 = i & 63;
        *(float4*)&s.hs[n][c4 * 4] = hs4[i];
    }
    const float4* if4 = (const float4*)(img_feat + (size_t)b * Ll * Dd);
    for (int i = tid; i < Ll * 64; i += 768) {
        int l = i >> 6, c4 = i & 63;
        *(float4*)&s.iff[l][c4 * 4] = if4[i];
    }
    if (tid < Dd) { s.w1[tid] = W1[tid]; s.w2[tid] = W2[tid]; }
    if (tid < Nn) s.tgt[tid] = targets[b * Nn + tid];

    // ---- absorbed w_vector gather: out_WV[b] = wv[targets[b]] ----
    {
        const float4* wv4 = (const float4*)wv;
        float4* o4 = (float4*)(out + O_WV) + (size_t)b * 2250;
#pragma unroll
        for (int k = 0; k < 3; k++) {
            int i = tid + k * 768;
            if (i < 2250) {
                int row = i / 75, q2 = i - row * 75;
                int t = __ldg(&targets[b * Nn + row]);
                o4[i] = wv4[(size_t)t * 75 + q2];
            }
        }
    }
    __syncthreads();

    if (wid < 10) {
        // ---- Phase B: logits[l][n] = (iff[l] . hs[n]) / 16 ----
        // lane = n (30 active). Warp owns 5 l rows; hs LDS conflict-free,
        // iff LDS broadcast, packed-f32 FFMA2.
        int l0 = wid * 5;
        int nl = lane < Nn ? lane : 0;
        const ulonglong2* hrow = (const ulonglong2*)&s.hs[nl][0];
        unsigned long long a01[5], a23[5];
#pragma unroll
        for (int li = 0; li < 5; li++) { a01[li] = 0ull; a23[li] = 0ull; }
        for (int c4 = 0; c4 < 64; c4++) {
            ulonglong2 h = hrow[c4];
#pragma unroll
            for (int li = 0; li < 5; li++) {
                int l = l0 + li; if (l > 48) l = 48;      // clamp (wid9,li4)
                ulonglong2 a = *(const ulonglong2*)&s.iff[l][c4 * 4];
                fma2(a01[li], a.x, h.x);
                fma2(a23[li], a.y, h.y);
            }
        }
        if (lane < Nn) {
#pragma unroll
            for (int li = 0; li < 5; li++) {
                int l = l0 + li;
                if (l < Ll)
                    s.logits[l][lane] = f32x2_hsum(a01[li], a23[li]) * 0.0625f;
            }
        }
    } else {
        // ---- Phase A: per-row dots on warps 10..23, float4-vectorized ----
        const float4* tat4 = (const float4*)(tat + (size_t)b * Nn * Dd);
        float4 w1a = *(const float4*)&s.w1[lane * 4];
        float4 w1b = *(const float4*)&s.w1[lane * 4 + 128];
        float4 w2a = *(const float4*)&s.w2[lane * 4];
        float4 w2b = *(const float4*)&s.w2[lane * 4 + 128];
        for (int t = wid - 10; t < Nn + Ll; t += 14) {
            if (t < Nn) {
                int n = t;
                float4 t0 = tat4[n * 64 + lane];
                float4 t1 = tat4[n * 64 + lane + 32];
                float4 h0 = *(const float4*)&s.hs[n][lane * 4];
                float4 h1 = *(const float4*)&s.hs[n][lane * 4 + 128];
                float a1 = dot4(h0, w1a) + dot4(h1, w1b);
                float a2 =
                    fast_tanh(t0.x + h0.x) * w2a.x + fast_tanh(t0.y + h0.y) * w2a.y +
                    fast_tanh(t0.z + h0.z) * w2a.z + fast_tanh(t0.w + h0.w) * w2a.w +
                    fast_tanh(t1.x + h1.x) * w2b.x + fast_tanh(t1.y + h1.y) * w2b.y +
                    fast_tanh(t1.z + h1.z) * w2b.z + fast_tanh(t1.w + h1.w) * w2b.w;
                a1 = warp_red(a1);
                a2 = warp_red(a2);
                if (lane == 0) { s.hsW1[n] = a1; s.tl[n] = a2; }
            } else {
                int l = t - Nn;
                float4 f0 = *(const float4*)&s.iff[l][lane * 4];
                float4 f1 = *(const float4*)&s.iff[l][lane * 4 + 128];
                float a = dot4(f0, w1a) + dot4(f1, w1b);
                a = warp_red(a);
                if (lane == 0) s.v2l[l] = a;
            }
        }
    }
    __syncthreads();

    // ---- Phase C: per-l softmax over n fused with s_v logit ----
    if (tid < Ll) {
        int l = tid;
        float m = -1e30f;
#pragma unroll
        for (int n = 0; n < Nn; n++) m = fmaxf(m, s.logits[l][n]);
        float sum = 0.f, acc = 0.f;
#pragma unroll
        for (int n = 0; n < Nn; n++) {
            float e = __expf(s.logits[l][n] - m);
            sum += e;
            acc += e * s.hsW1[n];
        }
        s.svl[l] = acc / sum;
    }
    __syncthreads();

    // ---- Phase D: the three softmaxes ----
    if (wid == 0) warp_softmax(s.svl, s.sv, out + O_SV + b * Ll, Ll, lane);
    if (wid == 1) warp_softmax(s.v2l, 0, out + O_SV2 + b * Ll, Ll, lane);
    if (wid == 2) warp_softmax(s.tl, s.st, out + O_ST + b * Nn, Nn, lane);
    __syncthreads();

    // ---- Phase E: out_img_vec and s_t-weighted word vectors ----
    if (tid < Dd) {
        float a = 0.f;
#pragma unroll
        for (int l = 0; l < Ll; l++) a += s.sv[l] * s.iff[l][tid];
        s.oiv[tid] = a;
    }
    if (tid >= 256 && tid < 256 + WDc) {
        int w = tid - 256;
        float a = 0.f;
#pragma unroll
        for (int n = 0; n < Nn; n++)
            a += s.st[n] * __ldg(&wv[(size_t)s.tgt[n] * WDc + w]);
        s.svwv[w] = a;
    }

    // ---- wait for precompute blocks (overlapped with phases A-E) ----
    if (tid == 0) {
        while (*((volatile unsigned*)&g_cnt) < (unsigned)G_PRE) {}
        __threadfence();
    }
    __syncthreads();

    // ---- Phase F: final sigmoid heads (warp-dot per k, via g_M) ----
    for (int k = wid; k < NBc; k += 24) {
        float a = 0.f;
        for (int w = lane; w < WDc; w += 32) a += s.svwv[w] * g_M[k * WDc + w];
        float a2 = 0.f;
#pragma unroll
        for (int c = lane; c < Dd; c += 32) a2 += s.oiv[c] * Whi[k * Dd + c];
        a = warp_red(a);
        a2 = warp_red(a2);
        if (lane == 0) {
            out[O_TGT + b * NBc + k] = 1.f / (1.f + __expf(-(a + g_bb[k])));
            out[O_IMG + b * NBc + k] = 1.f / (1.f + __expf(-(a2 + bhi[k])));
        }
    }
}

// ---------------------------------------------------------------------------
extern "C" void kernel_launch(void* const* d_in, const int* in_sizes, int n_in,
                              void* d_out, int out_size) {
    const float* rel     = (const float*)d_in[0];
    const float* wv      = (const float*)d_in[1];
    const float* img     = (const float*)d_in[2];
    const float* hs      = (const float*)d_in[3];
    const float* tat     = (const float*)d_in[4];
    const float* Wc      = (const float*)d_in[5];
    const float* bc      = (const float*)d_in[6];
    const float* W1      = (const float*)d_in[7];
    const float* W2      = (const float*)d_in[8];
    const float* Whi     = (const float*)d_in[9];
    const float* bhi     = (const float*)d_in[10];
    const float* Wht     = (const float*)d_in[11];
    const float* bht     = (const float*)d_in[12];
    const int*   targets = (const int*)d_in[13];
    const int*   lengths = (const int*)d_in[14];
    float* out = (float*)d_out;

    cudaFuncSetAttribute(fused_kernel,
                         cudaFuncAttributeMaxDynamicSharedMemorySize,
                         (int)sizeof(SmemC));

    fused_kernel<<<G_TOTAL, 768, sizeof(SmemC)>>>(
        rel, wv, img, hs, tat, Wc, bc, W1, W2, Whi, bhi, Wht, bht,
        targets, lengths, out);
}

// round 15
// speedup vs baseline: 1.1919x; 1.1919x over previous
#include <cuda_runtime.h>
#include <math.h>

#define Bb 256
#define Nn 30
#define Ll 49
#define Vv 2000
#define WDc 300
#define Dd 256
#define NBc 64
#define Rr 50

// Output layout (concatenated flattened outputs in reference return order)
#define O_IMG 0
#define O_TGT (Bb*NBc)                  // 16384
#define O_WV  (2*Bb*NBc)                // 32768
#define O_SV  (O_WV + Bb*Nn*WDc)        // 2336768
#define O_ST  (O_SV + Bb*Ll)            // 2349312
#define O_SV2 (O_ST + Bb*Nn)            // 2356992
#define O_KG  (O_SV2 + Bb*Ll)           // 2369536

// Grid: [0,256) batch | [256,320) precompute | [320,576) kg
// Batch first => all 256 batch blocks resident in wave 0 (296 slots);
// pre+kg backfill behind them.
#define G_BATCH 256
#define G_PRE   64
#define G_KG    256
#define G_TOTAL (G_BATCH + G_PRE + G_KG)

#define HS_S 260      // 65 x 16B units, 65%8==1 -> LDS.128 conflict-free
#define LG_S 33

__device__ float g_M[NBc*WDc];
__device__ float g_bb[NBc];
__device__ unsigned g_cnt;    // monotonic; never reset (g_M replay-invariant)

// NOTE: float4-accessed members (hs, iff, w1, w2) must sit at 16B-aligned
// offsets — keep them FIRST; scalar-only members follow.
struct __align__(16) SmemC {
    float hs[Nn][HS_S];     // offset 0          (31200 B, %16==0)
    float iff[Ll][HS_S];    // offset 31200      (50960 B, %16==0)
    float w1[Dd];           // offset 82160      (%16==0)
    float w2[Dd];           // offset 83184      (%16==0)
    float logits[Ll][LG_S]; // scalar access only
    float hsW1[Nn], tl[Nn], st[Nn];
    float v2l[Ll], svl[Ll], sv[Ll];
    float svwv[WDc];
    float oiv[Dd];
    int tgt[Nn];
};

__device__ __forceinline__ float fast_tanh(float x) {
    float r;
    asm("tanh.approx.f32 %0, %1;" : "=f"(r) : "f"(x));
    return r;
}

__device__ __forceinline__ float warp_red(float a) {
#pragma unroll
    for (int o = 16; o; o >>= 1) a += __shfl_xor_sync(0xffffffffu, a, o);
    return a;
}

__device__ __forceinline__ void fma2(unsigned long long& d,
                                     unsigned long long a,
                                     unsigned long long b) {
    asm("fma.rn.f32x2 %0, %1, %2, %0;" : "+l"(d) : "l"(a), "l"(b));
}

__device__ __forceinline__ float f32x2_hsum(unsigned long long a,
                                            unsigned long long b) {
    unsigned long long s;
    asm("add.rn.f32x2 %0, %1, %2;" : "=l"(s) : "l"(a), "l"(b));
    float lo, hi;
    asm("mov.b64 {%0, %1}, %2;" : "=f"(lo), "=f"(hi) : "l"(s));
    return lo + hi;
}

__device__ __forceinline__ float dot4(float4 a, float4 b) {
    return a.x * b.x + a.y * b.y + a.z * b.z + a.w * b.w;
}

__device__ __forceinline__ void warp_softmax(const float* src, float* dst_s,
                                             float* dst_g, int cnt, int lane) {
    float v0 = lane < cnt ? src[lane] : -1e30f;
    float v1 = (lane + 32) < cnt ? src[lane + 32] : -1e30f;
    float m = fmaxf(v0, v1);
#pragma unroll
    for (int o = 16; o; o >>= 1) m = fmaxf(m, __shfl_xor_sync(0xffffffffu, m, o));
    float e0 = lane < cnt ? __expf(v0 - m) : 0.f;
    float e1 = (lane + 32) < cnt ? __expf(v1 - m) : 0.f;
    float s = e0 + e1;
#pragma unroll
    for (int o = 16; o; o >>= 1) s += __shfl_xor_sync(0xffffffffu, s, o);
    float inv = 1.f / s;
    if (lane < cnt) {
        float r = e0 * inv;
        if (dst_s) dst_s[lane] = r;
        dst_g[lane] = r;
    }
    if (lane + 32 < cnt) {
        float r = e1 * inv;
        if (dst_s) dst_s[lane + 32] = r;
        dst_g[lane + 32] = r;
    }
}

// ---------------------------------------------------------------------------
// ONE kernel. Blocks: batch | precompute | kg.
// ---------------------------------------------------------------------------
__global__ __launch_bounds__(768, 2) void fused_kernel(
    const float* __restrict__ rel, const float* __restrict__ wv,
    const float* __restrict__ img_feat, const float* __restrict__ hs_g,
    const float* __restrict__ tat,
    const float* __restrict__ Wc, const float* __restrict__ bc,
    const float* __restrict__ W1, const float* __restrict__ W2,
    const float* __restrict__ Whi, const float* __restrict__ bhi,
    const float* __restrict__ Wht, const float* __restrict__ bht,
    const int* __restrict__ targets, const int* __restrict__ lengths,
    float* __restrict__ out) {
    extern __shared__ char smem_raw[];
    int bid = blockIdx.x;
    int tid = threadIdx.x;
    int lane = tid & 31, wid = tid >> 5;

    // ======================= PRECOMPUTE PART ===============================
    if (bid >= G_BATCH && bid < G_BATCH + G_PRE) {
        float* s_wht = (float*)smem_raw;     // 256 floats
        int k = bid - G_BATCH;
        if (tid < Dd) s_wht[tid] = Wht[k * Dd + tid];
        __syncthreads();
        if (tid < WDc) {
            float acc = 0.f;
#pragma unroll 16
            for (int c = 0; c < Dd; c++)
                acc += s_wht[c] * __ldg(&Wc[c * WDc + tid]);
            g_M[k * WDc + tid] = acc;
        }
        if (wid == 0) {
            float a = 0.f;
#pragma unroll
            for (int c = lane; c < Dd; c += 32) a += s_wht[c] * bc[c];
            a = warp_red(a);
            if (lane == 0) g_bb[k] = a + bht[k];
        }
        __syncthreads();
        if (tid == 0) {
            __threadfence();
            atomicAdd(&g_cnt, 1u);
        }
        return;
    }

    // ======================= KG PART =======================================
    // 1 block per b; 2 chunks of 15 i's; 15 loads in flight before stores.
    if (bid >= G_BATCH + G_PRE) {
        int b = bid - (G_BATCH + G_PRE);     // [0, 256)
        int* s_tj = (int*)smem_raw;
        __shared__ int s_len;
        if (tid < Nn) s_tj[tid] = targets[b * Nn + tid] - 4;
        if (tid == 0) s_len = lengths[b];
        __syncthreads();
        if (tid >= 750) return;
        int j = tid / 25;
        int r2 = tid - j * 25;
        int len = s_len;
        int c0 = s_tj[j] * 25 + r2;
        int lim = (j < len) ? len : 0;
        const float2* rel2 = (const float2*)rel;
        float2* o = (float2*)(out + O_KG) + (size_t)b * (Nn * 750) + tid;
#pragma unroll
        for (int ch = 0; ch < 2; ch++) {
            int i0 = ch * 15;
            float2 v[15];
#pragma unroll
            for (int k = 0; k < 15; k++) {
                int i = i0 + k;
                v[k] = make_float2(0.f, 0.f);
                if (i < lim) v[k] = rel2[s_tj[i] * 50000 + c0];
            }
#pragma unroll
            for (int k = 0; k < 15; k++) o[(i0 + k) * 750] = v[k];
        }
        return;
    }

    // ======================= BATCH PART ====================================
    SmemC& s = *(SmemC*)smem_raw;
    int b = bid;

    // ---- load phase ----
    const float4* hs4 = (const float4*)(hs_g + (size_t)b * Nn * Dd);
    for (int i = tid; i < Nn * 64; i += 768) {
        int n = i >> 6, c4 = i & 63;
        *(float4*)&s.hs[n][c4 * 4] = hs4[i];
    }
    const float4* if4 = (const float4*)(img_feat + (size_t)b * Ll * Dd);
    for (int i = tid; i < Ll * 64; i += 768) {
        int l = i >> 6, c4 = i & 63;
        *(float4*)&s.iff[l][c4 * 4] = if4[i];
    }
    if (tid < Dd) { s.w1[tid] = W1[tid]; s.w2[tid] = W2[tid]; }
    if (tid < Nn) s.tgt[tid] = targets[b * Nn + tid];

    // ---- absorbed w_vector gather: out_WV[b] = wv[targets[b]] ----
    {
        const float4* wv4 = (const float4*)wv;
        float4* o4 = (float4*)(out + O_WV) + (size_t)b * 2250;
#pragma unroll
        for (int k = 0; k < 3; k++) {
            int i = tid + k * 768;
            if (i < 2250) {
                int row = i / 75, q2 = i - row * 75;
                int t = __ldg(&targets[b * Nn + row]);
                o4[i] = wv4[(size_t)t * 75 + q2];
            }
        }
    }
    __syncthreads();

    if (wid < 10) {
        // ---- Phase B: logits[l][n] = (iff[l] . hs[n]) / 16 ----
        // lane = n (30 active). Warp owns 5 l rows; hs LDS conflict-free,
        // iff LDS broadcast, packed-f32 FFMA2.
        int l0 = wid * 5;
        int nl = lane < Nn ? lane : 0;
        const ulonglong2* hrow = (const ulonglong2*)&s.hs[nl][0];
        unsigned long long a01[5], a23[5];
#pragma unroll
        for (int li = 0; li < 5; li++) { a01[li] = 0ull; a23[li] = 0ull; }
        for (int c4 = 0; c4 < 64; c4++) {
            ulonglong2 h = hrow[c4];
#pragma unroll
            for (int li = 0; li < 5; li++) {
                int l = l0 + li; if (l > 48) l = 48;      // clamp (wid9,li4)
                ulonglong2 a = *(const ulonglong2*)&s.iff[l][c4 * 4];
                fma2(a01[li], a.x, h.x);
                fma2(a23[li], a.y, h.y);
            }
        }
        if (lane < Nn) {
#pragma unroll
            for (int li = 0; li < 5; li++) {
                int l = l0 + li;
                if (l < Ll)
                    s.logits[l][lane] = f32x2_hsum(a01[li], a23[li]) * 0.0625f;
            }
        }
    } else {
        // ---- Phase A: per-row dots on warps 10..23, float4-vectorized ----
        const float4* tat4 = (const float4*)(tat + (size_t)b * Nn * Dd);
        float4 w1a = *(const float4*)&s.w1[lane * 4];
        float4 w1b = *(const float4*)&s.w1[lane * 4 + 128];
        float4 w2a = *(const float4*)&s.w2[lane * 4];
        float4 w2b = *(const float4*)&s.w2[lane * 4 + 128];
        for (int t = wid - 10; t < Nn + Ll; t += 14) {
            if (t < Nn) {
                int n = t;
                float4 t0 = tat4[n * 64 + lane];
                float4 t1 = tat4[n * 64 + lane + 32];
                float4 h0 = *(const float4*)&s.hs[n][lane * 4];
                float4 h1 = *(const float4*)&s.hs[n][lane * 4 + 128];
                float a1 = dot4(h0, w1a) + dot4(h1, w1b);
                float a2 =
                    fast_tanh(t0.x + h0.x) * w2a.x + fast_tanh(t0.y + h0.y) * w2a.y +
                    fast_tanh(t0.z + h0.z) * w2a.z + fast_tanh(t0.w + h0.w) * w2a.w +
                    fast_tanh(t1.x + h1.x) * w2b.x + fast_tanh(t1.y + h1.y) * w2b.y +
                    fast_tanh(t1.z + h1.z) * w2b.z + fast_tanh(t1.w + h1.w) * w2b.w;
                a1 = warp_red(a1);
                a2 = warp_red(a2);
                if (lane == 0) { s.hsW1[n] = a1; s.tl[n] = a2; }
            } else {
                int l = t - Nn;
                float4 f0 = *(const float4*)&s.iff[l][lane * 4];
                float4 f1 = *(const float4*)&s.iff[l][lane * 4 + 128];
                float a = dot4(f0, w1a) + dot4(f1, w1b);
                a = warp_red(a);
                if (lane == 0) s.v2l[l] = a;
            }
        }
    }
    __syncthreads();

    // ---- Phase C: per-l softmax over n fused with s_v logit ----
    if (tid < Ll) {
        int l = tid;
        float m = -1e30f;
#pragma unroll
        for (int n = 0; n < Nn; n++) m = fmaxf(m, s.logits[l][n]);
        float sum = 0.f, acc = 0.f;
#pragma unroll
        for (int n = 0; n < Nn; n++) {
            float e = __expf(s.logits[l][n] - m);
            sum += e;
            acc += e * s.hsW1[n];
        }
        s.svl[l] = acc / sum;
    }
    __syncthreads();

    // ---- Phase D: the three softmaxes ----
    if (wid == 0) warp_softmax(s.svl, s.sv, out + O_SV + b * Ll, Ll, lane);
    if (wid == 1) warp_softmax(s.v2l, 0, out + O_SV2 + b * Ll, Ll, lane);
    if (wid == 2) warp_softmax(s.tl, s.st, out + O_ST + b * Nn, Nn, lane);
    __syncthreads();

    // ---- Phase E: out_img_vec and s_t-weighted word vectors ----
    if (tid < Dd) {
        float a = 0.f;
#pragma unroll
        for (int l = 0; l < Ll; l++) a += s.sv[l] * s.iff[l][tid];
        s.oiv[tid] = a;
    }
    if (tid >= 256 && tid < 256 + WDc) {
        int w = tid - 256;
        float a = 0.f;
#pragma unroll
        for (int n = 0; n < Nn; n++)
            a += s.st[n] * __ldg(&wv[(size_t)s.tgt[n] * WDc + w]);
        s.svwv[w] = a;
    }

    // ---- wait for precompute blocks (overlapped with phases A-E) ----
    if (tid == 0) {
        while (*((volatile unsigned*)&g_cnt) < (unsigned)G_PRE) {}
        __threadfence();
    }
    __syncthreads();

    // ---- Phase F: final sigmoid heads (warp-dot per k, via g_M) ----
    for (int k = wid; k < NBc; k += 24) {
        float a = 0.f;
        for (int w = lane; w < WDc; w += 32) a += s.svwv[w] * g_M[k * WDc + w];
        float a2 = 0.f;
#pragma unroll
        for (int c = lane; c < Dd; c += 32) a2 += s.oiv[c] * Whi[k * Dd + c];
        a = warp_red(a);
        a2 = warp_red(a2);
        if (lane == 0) {
            out[O_TGT + b * NBc + k] = 1.f / (1.f + __expf(-(a + g_bb[k])));
            out[O_IMG + b * NBc + k] = 1.f / (1.f + __expf(-(a2 + bhi[k])));
        }
    }
}

// ---------------------------------------------------------------------------
extern "C" void kernel_launch(void* const* d_in, const int* in_sizes, int n_in,
                              void* d_out, int out_size) {
    const float* rel     = (const float*)d_in[0];
    const float* wv      = (const float*)d_in[1];
    const float* img     = (const float*)d_in[2];
    const float* hs      = (const float*)d_in[3];
    const float* tat     = (const float*)d_in[4];
    const float* Wc      = (const float*)d_in[5];
    const float* bc      = (const float*)d_in[6];
    const float* W1      = (const float*)d_in[7];
    const float* W2      = (const float*)d_in[8];
    const float* Whi     = (const float*)d_in[9];
    const float* bhi     = (const float*)d_in[10];
    const float* Wht     = (const float*)d_in[11];
    const float* bht     = (const float*)d_in[12];
    const int*   targets = (const int*)d_in[13];
    const int*   lengths = (const int*)d_in[14];
    float* out = (float*)d_out;

    cudaFuncSetAttribute(fused_kernel,
                         cudaFuncAttributeMaxDynamicSharedMemorySize,
                         (int)sizeof(SmemC));

    fused_kernel<<<G_TOTAL, 768, sizeof(SmemC)>>>(
        rel, wv, img, hs, tat, Wc, bc, W1, W2, Whi, bhi, Wht, bht,
        targets, lengths, out);
}

// round 16
// speedup vs baseline: 1.3487x; 1.1316x over previous
#include <cuda_runtime.h>
#include <math.h>

#define Bb 256
#define Nn 30
#define Ll 49
#define Vv 2000
#define WDc 300
#define Dd 256
#define NBc 64
#define Rr 50

// Output layout (concatenated flattened outputs in reference return order)
#define O_IMG 0
#define O_TGT (Bb*NBc)                  // 16384
#define O_WV  (2*Bb*NBc)                // 32768
#define O_SV  (O_WV + Bb*Nn*WDc)        // 2336768
#define O_ST  (O_SV + Bb*Ll)            // 2349312
#define O_SV2 (O_ST + Bb*Nn)            // 2356992
#define O_KG  (O_SV2 + Bb*Ll)           // 2369536

// Grid: [0,256) batch (with inline kg + wv gather) | [256,320) precompute
#define G_BATCH 256
#define G_PRE   64
#define G_TOTAL (G_BATCH + G_PRE)

#define HS_S 260      // 65 x 16B units, 65%8==1 -> LDS.128 conflict-free
#define LG_S 33

__device__ float g_M[NBc*WDc];
__device__ float g_bb[NBc];
__device__ unsigned g_cnt;    // monotonic; never reset (g_M replay-invariant)

// NOTE: float4-accessed members (hs, iff, w1, w2) must sit at 16B-aligned
// offsets — keep them FIRST; scalar-only members follow.
struct __align__(16) SmemC {
    float hs[Nn][HS_S];     // offset 0          (31200 B, %16==0)
    float iff[Ll][HS_S];    // offset 31200      (50960 B, %16==0)
    float w1[Dd];           // offset 82160      (%16==0)
    float w2[Dd];           // offset 83184      (%16==0)
    float logits[Ll][LG_S]; // scalar access only
    float hsW1[Nn], tl[Nn], st[Nn];
    float v2l[Ll], svl[Ll], sv[Ll];
    float svwv[WDc];
    float oiv[Dd];
    int tgt[Nn];
};

__device__ __forceinline__ float fast_tanh(float x) {
    float r;
    asm("tanh.approx.f32 %0, %1;" : "=f"(r) : "f"(x));
    return r;
}

__device__ __forceinline__ float warp_red(float a) {
#pragma unroll
    for (int o = 16; o; o >>= 1) a += __shfl_xor_sync(0xffffffffu, a, o);
    return a;
}

__device__ __forceinline__ void fma2(unsigned long long& d,
                                     unsigned long long a,
                                     unsigned long long b) {
    asm("fma.rn.f32x2 %0, %1, %2, %0;" : "+l"(d) : "l"(a), "l"(b));
}

__device__ __forceinline__ float f32x2_hsum(unsigned long long a,
                                            unsigned long long b) {
    unsigned long long s;
    asm("add.rn.f32x2 %0, %1, %2;" : "=l"(s) : "l"(a), "l"(b));
    float lo, hi;
    asm("mov.b64 {%0, %1}, %2;" : "=f"(lo), "=f"(hi) : "l"(s));
    return lo + hi;
}

__device__ __forceinline__ float dot4(float4 a, float4 b) {
    return a.x * b.x + a.y * b.y + a.z * b.z + a.w * b.w;
}

__device__ __forceinline__ void warp_softmax(const float* src, float* dst_s,
                                             float* dst_g, int cnt, int lane) {
    float v0 = lane < cnt ? src[lane] : -1e30f;
    float v1 = (lane + 32) < cnt ? src[lane + 32] : -1e30f;
    float m = fmaxf(v0, v1);
#pragma unroll
    for (int o = 16; o; o >>= 1) m = fmaxf(m, __shfl_xor_sync(0xffffffffu, m, o));
    float e0 = lane < cnt ? __expf(v0 - m) : 0.f;
    float e1 = (lane + 32) < cnt ? __expf(v1 - m) : 0.f;
    float s = e0 + e1;
#pragma unroll
    for (int o = 16; o; o >>= 1) s += __shfl_xor_sync(0xffffffffu, s, o);
    float inv = 1.f / s;
    if (lane < cnt) {
        float r = e0 * inv;
        if (dst_s) dst_s[lane] = r;
        dst_g[lane] = r;
    }
    if (lane + 32 < cnt) {
        float r = e1 * inv;
        if (dst_s) dst_s[lane + 32] = r;
        dst_g[lane + 32] = r;
    }
}

// ---------------------------------------------------------------------------
// ONE kernel. Blocks: batch (inline kg via warp specialization) | precompute.
// ---------------------------------------------------------------------------
__global__ __launch_bounds__(768, 2) void fused_kernel(
    const float* __restrict__ rel, const float* __restrict__ wv,
    const float* __restrict__ img_feat, const float* __restrict__ hs_g,
    const float* __restrict__ tat,
    const float* __restrict__ Wc, const float* __restrict__ bc,
    const float* __restrict__ W1, const float* __restrict__ W2,
    const float* __restrict__ Whi, const float* __restrict__ bhi,
    const float* __restrict__ Wht, const float* __restrict__ bht,
    const int* __restrict__ targets, const int* __restrict__ lengths,
    float* __restrict__ out) {
    extern __shared__ char smem_raw[];
    int bid = blockIdx.x;
    int tid = threadIdx.x;
    int lane = tid & 31, wid = tid >> 5;

    // ======================= PRECOMPUTE PART ===============================
    if (bid >= G_BATCH) {
        float* s_wht = (float*)smem_raw;     // 256 floats
        int k = bid - G_BATCH;
        if (tid < Dd) s_wht[tid] = Wht[k * Dd + tid];
        __syncthreads();
        if (tid < WDc) {
            float acc = 0.f;
#pragma unroll 16
            for (int c = 0; c < Dd; c++)
                acc += s_wht[c] * __ldg(&Wc[c * WDc + tid]);
            g_M[k * WDc + tid] = acc;
        }
        if (wid == 0) {
            float a = 0.f;
#pragma unroll
            for (int c = lane; c < Dd; c += 32) a += s_wht[c] * bc[c];
            a = warp_red(a);
            if (lane == 0) g_bb[k] = a + bht[k];
        }
        __syncthreads();
        if (tid == 0) {
            __threadfence();
            atomicAdd(&g_cnt, 1u);
        }
        return;
    }

    // ======================= BATCH PART ====================================
    SmemC& s = *(SmemC*)smem_raw;
    int b = bid;

    // ---- load phase ----
    const float4* hs4 = (const float4*)(hs_g + (size_t)b * Nn * Dd);
    for (int i = tid; i < Nn * 64; i += 768) {
        int n = i >> 6, c4 = i & 63;
        *(float4*)&s.hs[n][c4 * 4] = hs4[i];
    }
    const float4* if4 = (const float4*)(img_feat + (size_t)b * Ll * Dd);
    for (int i = tid; i < Ll * 64; i += 768) {
        int l = i >> 6, c4 = i & 63;
        *(float4*)&s.iff[l][c4 * 4] = if4[i];
    }
    if (tid < Dd) { s.w1[tid] = W1[tid]; s.w2[tid] = W2[tid]; }
    if (tid < Nn) s.tgt[tid] = targets[b * Nn + tid];

    // ---- absorbed w_vector gather: out_WV[b] = wv[targets[b]] ----
    {
        const float4* wv4 = (const float4*)wv;
        float4* o4 = (float4*)(out + O_WV) + (size_t)b * 2250;
#pragma unroll
        for (int k = 0; k < 3; k++) {
            int i = tid + k * 768;
            if (i < 2250) {
                int row = i / 75, q2 = i - row * 75;
                int t = __ldg(&targets[b * Nn + row]);
                o4[i] = wv4[(size_t)t * 75 + q2];
            }
        }
    }
    __syncthreads();

    if (wid < 10) {
        // ---- Phase B: logits[l][n] = (iff[l] . hs[n]) / 16 ----
        // lane = n (30 active). Warp owns 5 l rows; hs LDS conflict-free,
        // iff LDS broadcast, packed-f32 FFMA2.
        int l0 = wid * 5;
        int nl = lane < Nn ? lane : 0;
        const ulonglong2* hrow = (const ulonglong2*)&s.hs[nl][0];
        unsigned long long a01[5], a23[5];
#pragma unroll
        for (int li = 0; li < 5; li++) { a01[li] = 0ull; a23[li] = 0ull; }
        for (int c4 = 0; c4 < 64; c4++) {
            ulonglong2 h = hrow[c4];
#pragma unroll
            for (int li = 0; li < 5; li++) {
                int l = l0 + li; if (l > 48) l = 48;      // clamp (wid9,li4)
                ulonglong2 a = *(const ulonglong2*)&s.iff[l][c4 * 4];
                fma2(a01[li], a.x, h.x);
                fma2(a23[li], a.y, h.y);
            }
        }
        if (lane < Nn) {
#pragma unroll
            for (int li = 0; li < 5; li++) {
                int l = l0 + li;
                if (l < Ll)
                    s.logits[l][lane] = f32x2_hsum(a01[li], a23[li]) * 0.0625f;
            }
        }
    } else if (wid < 17) {
        // ---- Phase A: per-row dots on warps 10..16, float4-vectorized ----
        const float4* tat4 = (const float4*)(tat + (size_t)b * Nn * Dd);
        float4 w1a = *(const float4*)&s.w1[lane * 4];
        float4 w1b = *(const float4*)&s.w1[lane * 4 + 128];
        float4 w2a = *(const float4*)&s.w2[lane * 4];
        float4 w2b = *(const float4*)&s.w2[lane * 4 + 128];
        for (int t = wid - 10; t < Nn + Ll; t += 7) {
            if (t < Nn) {
                int n = t;
                float4 t0 = tat4[n * 64 + lane];
                float4 t1 = tat4[n * 64 + lane + 32];
                float4 h0 = *(const float4*)&s.hs[n][lane * 4];
                float4 h1 = *(const float4*)&s.hs[n][lane * 4 + 128];
                float a1 = dot4(h0, w1a) + dot4(h1, w1b);
                float a2 =
                    fast_tanh(t0.x + h0.x) * w2a.x + fast_tanh(t0.y + h0.y) * w2a.y +
                    fast_tanh(t0.z + h0.z) * w2a.z + fast_tanh(t0.w + h0.w) * w2a.w +
                    fast_tanh(t1.x + h1.x) * w2b.x + fast_tanh(t1.y + h1.y) * w2b.y +
                    fast_tanh(t1.z + h1.z) * w2b.z + fast_tanh(t1.w + h1.w) * w2b.w;
                a1 = warp_red(a1);
                a2 = warp_red(a2);
                if (lane == 0) { s.hsW1[n] = a1; s.tl[n] = a2; }
            } else {
                int l = t - Nn;
                float4 f0 = *(const float4*)&s.iff[l][lane * 4];
                float4 f1 = *(const float4*)&s.iff[l][lane * 4 + 128];
                float a = dot4(f0, w1a) + dot4(f1, w1b);
                a = warp_red(a);
                if (lane == 0) s.v2l[l] = a;
            }
        }
    } else {
        // ---- KG: warps 17..23 (224 threads) do block b's KG gather ----
        // Overlaps DRAM latency with Phase A/B compute in the same block.
        int wtid = tid - 544;                 // [0, 224)
        int len = __ldg(&lengths[b]);
        const float2* rel2 = (const float2*)rel;
        float2* okg = (float2*)(out + O_KG) + (size_t)b * (Nn * 750);
        for (int sIdx = wtid; sIdx < 750; sIdx += 224) {
            int j = sIdx / 25;
            int r2 = sIdx - j * 25;
            int c0 = (s.tgt[j] - 4) * 25 + r2;
            int lim = (j < len) ? len : 0;
            float2* o = okg + sIdx;
#pragma unroll
            for (int ch = 0; ch < 2; ch++) {
                int i0 = ch * 15;
                float2 v[15];
#pragma unroll
                for (int k = 0; k < 15; k++) {
                    int i = i0 + k;
                    v[k] = make_float2(0.f, 0.f);
                    if (i < lim) v[k] = rel2[(s.tgt[i] - 4) * 50000 + c0];
                }
#pragma unroll
                for (int k = 0; k < 15; k++) o[(i0 + k) * 750] = v[k];
            }
        }
    }
    __syncthreads();

    // ---- Phase C: per-l softmax over n fused with s_v logit ----
    if (tid < Ll) {
        int l = tid;
        float m = -1e30f;
#pragma unroll
        for (int n = 0; n < Nn; n++) m = fmaxf(m, s.logits[l][n]);
        float sum = 0.f, acc = 0.f;
#pragma unroll
        for (int n = 0; n < Nn; n++) {
            float e = __expf(s.logits[l][n] - m);
            sum += e;
            acc += e * s.hsW1[n];
        }
        s.svl[l] = acc / sum;
    }
    __syncthreads();

    // ---- Phase D: the three softmaxes ----
    if (wid == 0) warp_softmax(s.svl, s.sv, out + O_SV + b * Ll, Ll, lane);
    if (wid == 1) warp_softmax(s.v2l, 0, out + O_SV2 + b * Ll, Ll, lane);
    if (wid == 2) warp_softmax(s.tl, s.st, out + O_ST + b * Nn, Nn, lane);
    __syncthreads();

    // ---- Phase E: out_img_vec and s_t-weighted word vectors ----
    if (tid < Dd) {
        float a = 0.f;
#pragma unroll
        for (int l = 0; l < Ll; l++) a += s.sv[l] * s.iff[l][tid];
        s.oiv[tid] = a;
    }
    if (tid >= 256 && tid < 256 + WDc) {
        int w = tid - 256;
        float a = 0.f;
#pragma unroll
        for (int n = 0; n < Nn; n++)
            a += s.st[n] * __ldg(&wv[(size_t)s.tgt[n] * WDc + w]);
        s.svwv[w] = a;
    }

    // ---- wait for precompute blocks (overlapped with phases A-E) ----
    if (tid == 0) {
        while (*((volatile unsigned*)&g_cnt) < (unsigned)G_PRE) {}
        __threadfence();
    }
    __syncthreads();

    // ---- Phase F: final sigmoid heads (warp-dot per k, via g_M) ----
    for (int k = wid; k < NBc; k += 24) {
        float a = 0.f;
        for (int w = lane; w < WDc; w += 32) a += s.svwv[w] * g_M[k * WDc + w];
        float a2 = 0.f;
#pragma unroll
        for (int c = lane; c < Dd; c += 32) a2 += s.oiv[c] * Whi[k * Dd + c];
        a = warp_red(a);
        a2 = warp_red(a2);
        if (lane == 0) {
            out[O_TGT + b * NBc + k] = 1.f / (1.f + __expf(-(a + g_bb[k])));
            out[O_IMG + b * NBc + k] = 1.f / (1.f + __expf(-(a2 + bhi[k])));
        }
    }
}

// ---------------------------------------------------------------------------
extern "C" void kernel_launch(void* const* d_in, const int* in_sizes, int n_in,
                              void* d_out, int out_size) {
    const float* rel     = (const float*)d_in[0];
    const float* wv      = (const float*)d_in[1];
    const float* img     = (const float*)d_in[2];
    const float* hs      = (const float*)d_in[3];
    const float* tat     = (const float*)d_in[4];
    const float* Wc      = (const float*)d_in[5];
    const float* bc      = (const float*)d_in[6];
    const float* W1      = (const float*)d_in[7];
    const float* W2      = (const float*)d_in[8];
    const float* Whi     = (const float*)d_in[9];
    const float* bhi     = (const float*)d_in[10];
    const float* Wht     = (const float*)d_in[11];
    const float* bht     = (const float*)d_in[12];
    const int*   targets = (const int*)d_in[13];
    const int*   lengths = (const int*)d_in[14];
    float* out = (float*)d_out;

    cudaFuncSetAttribute(fused_kernel,
                         cudaFuncAttributeMaxDynamicSharedMemorySize,
                         (int)sizeof(SmemC));

    fused_kernel<<<G_TOTAL, 768, sizeof(SmemC)>>>(
        rel, wv, img, hs, tat, Wc, bc, W1, W2, Whi, bhi, Wht, bht,
        targets, lengths, out);
}